// round 1
// baseline (speedup 1.0000x reference)
#include <cuda_runtime.h>
#include <float.h>

#define N_PTS 131072
#define K_EMB 1024
#define D_DIM 64
#define TE    128          // embeddings per smem tile
#define BLOCK 128

#define DECAY 0.99f
#define ONE_MINUS_DECAY (1.0f - 0.99f)
#define EPSV 1e-5f

// -------- scratch (device globals: no allocation allowed) --------
__device__ float g_counts[K_EMB];
__device__ float g_embed_sum[K_EMB * D_DIM];
__device__ float g_enorm[K_EMB];
__device__ float g_loss_sum;

// -------- prep: zero scratch, precompute ||e||^2 --------
__global__ void prep_kernel(const float* __restrict__ emb) {
    int t = blockIdx.x * blockDim.x + threadIdx.x;   // 65536 threads
    if (t < K_EMB * D_DIM) g_embed_sum[t] = 0.f;
    if (t < K_EMB) {
        g_counts[t] = 0.f;
        const float4* row = (const float4*)(emb + (size_t)t * D_DIM);
        float s = 0.f;
        #pragma unroll
        for (int q = 0; q < 16; q++) {
            float4 v = row[q];
            s += v.x * v.x + v.y * v.y + v.z * v.z + v.w * v.w;
        }
        g_enorm[t] = s;
    }
    if (t == 0) g_loss_sum = 0.f;
}

// -------- main: argmin + gather + segment-sum atomics + loss --------
__global__ __launch_bounds__(BLOCK) void vq_main(
    const float* __restrict__ z, const float* __restrict__ emb,
    float* __restrict__ out_zq, float* __restrict__ out_idx)
{
    __shared__ float semb[TE * D_DIM];
    __shared__ float snorm[TE];
    __shared__ float sred[BLOCK];

    const int pt = blockIdx.x * BLOCK + threadIdx.x;

    // z row -> 64 registers
    float4 zr[16];
    const float4* zrow = (const float4*)(z + (size_t)pt * D_DIM);
    #pragma unroll
    for (int q = 0; q < 16; q++) zr[q] = zrow[q];

    float best = FLT_MAX;
    int bi = 0;

    for (int t0 = 0; t0 < K_EMB; t0 += TE) {
        __syncthreads();
        // cooperative coalesced tile load: TE*64 floats = 2048 float4
        {
            const float4* src = (const float4*)(emb + (size_t)t0 * D_DIM);
            float4* dst = (float4*)semb;
            #pragma unroll
            for (int q = 0; q < (TE * D_DIM / 4) / BLOCK; q++)   // 16
                dst[q * BLOCK + threadIdx.x] = src[q * BLOCK + threadIdx.x];
            if (threadIdx.x < TE) snorm[threadIdx.x] = g_enorm[t0 + threadIdx.x];
        }
        __syncthreads();

        #pragma unroll 2
        for (int e = 0; e < TE; e++) {
            const float4* er = (const float4*)(semb + e * D_DIM);
            float a0 = 0.f, a1 = 0.f, a2 = 0.f, a3 = 0.f;
            #pragma unroll
            for (int q = 0; q < 16; q++) {
                float4 ev = er[q];   // broadcast LDS.128, conflict-free
                float4 zv = zr[q];
                a0 = fmaf(ev.x, zv.x, a0);
                a1 = fmaf(ev.y, zv.y, a1);
                a2 = fmaf(ev.z, zv.z, a2);
                a3 = fmaf(ev.w, zv.w, a3);
            }
            float score = snorm[e] - 2.f * ((a0 + a1) + (a2 + a3));
            if (score < best) { best = score; bi = t0 + e; }
        }
    }

    // ---- epilogue ----
    out_idx[pt] = (float)bi;

    const float4* qrow = (const float4*)(emb + (size_t)bi * D_DIM);
    float4* orow = (float4*)(out_zq + (size_t)pt * D_DIM);
    float* esum = g_embed_sum + (size_t)bi * D_DIM;

    float lsum = 0.f;
    #pragma unroll
    for (int q = 0; q < 16; q++) {
        float4 qv = qrow[q];
        float4 zv = zr[q];
        orow[q] = qv;
        float dx = zv.x - qv.x, dy = zv.y - qv.y;
        float dz2 = zv.z - qv.z, dw = zv.w - qv.w;
        lsum += dx * dx + dy * dy + dz2 * dz2 + dw * dw;
        atomicAdd(esum + q * 4 + 0, zv.x);
        atomicAdd(esum + q * 4 + 1, zv.y);
        atomicAdd(esum + q * 4 + 2, zv.z);
        atomicAdd(esum + q * 4 + 3, zv.w);
    }
    atomicAdd(&g_counts[bi], 1.f);

    // block-reduce loss, one global atomic per CTA
    sred[threadIdx.x] = lsum;
    __syncthreads();
    for (int s = BLOCK / 2; s > 0; s >>= 1) {
        if (threadIdx.x < s) sred[threadIdx.x] += sred[threadIdx.x + s];
        __syncthreads();
    }
    if (threadIdx.x == 0) atomicAdd(&g_loss_sum, sred[0]);
}

// -------- finalize: EMA updates, normalization, loss mean --------
__global__ __launch_bounds__(1024) void finalize_kernel(
    const float* __restrict__ cluster_size, const float* __restrict__ ema,
    float* __restrict__ out_loss, float* __restrict__ out_nemb,
    float* __restrict__ out_ncs, float* __restrict__ out_nema)
{
    __shared__ float sred[1024];
    const int t = threadIdx.x;   // one CTA, 1024 threads (== K)

    float c = cluster_size[t] * DECAY + ONE_MINUS_DECAY * g_counts[t];
    out_ncs[t] = c;
    sred[t] = c;
    __syncthreads();
    for (int s = 512; s > 0; s >>= 1) {
        if (t < s) sred[t] += sred[t + s];
        __syncthreads();
    }
    float n = sred[0];
    float cs = (c + EPSV) / (n + (float)K_EMB * EPSV) * n;
    float inv = 1.f / cs;

    #pragma unroll 4
    for (int q = 0; q < D_DIM; q++) {
        int idx = t * D_DIM + q;
        float s = ema[idx] * DECAY + ONE_MINUS_DECAY * g_embed_sum[idx];
        out_nema[idx] = s;
        out_nemb[idx] = s * inv;
    }
    if (t == 0) out_loss[0] = g_loss_sum / (float)((size_t)N_PTS * D_DIM);
}

// -------- launch --------
extern "C" void kernel_launch(void* const* d_in, const int* in_sizes, int n_in,
                              void* d_out, int out_size) {
    const float* z   = (const float*)d_in[0];
    const float* emb = (const float*)d_in[1];
    const float* cs  = (const float*)d_in[2];
    const float* ema = (const float*)d_in[3];

    float* out      = (float*)d_out;
    float* out_zq   = out;                               // N*D
    float* out_loss = out + (size_t)N_PTS * D_DIM;       // 1
    float* out_idx  = out_loss + 1;                      // N
    float* out_nemb = out_idx + N_PTS;                   // K*D
    float* out_ncs  = out_nemb + (size_t)K_EMB * D_DIM;  // K
    float* out_nema = out_ncs + K_EMB;                   // K*D

    prep_kernel<<<256, 256>>>(emb);
    vq_main<<<N_PTS / BLOCK, BLOCK>>>(z, emb, out_zq, out_idx);
    finalize_kernel<<<1, 1024>>>(cs, ema, out_loss, out_nemb, out_ncs, out_nema);
}